// round 1
// baseline (speedup 1.0000x reference)
#include <cuda_runtime.h>
#include <cuda_bf16.h>
#include <math.h>

// ---------------- problem constants ----------------
constexpr int N_   = 20000;   // nodes
constexpr int E_   = 100000;  // edges
constexpr int D_   = 248;     // Lie algebra dim
constexpr int HID_ = 256;     // MLP hidden
constexpr int IN_  = 128;     // input feature dim
constexpr int OUT_ = 16;      // output dim
constexpr int NL_  = 4;       // layers
constexpr int NNZ_ = 512;     // structure constant nnz
constexpr int NB_  = 1024;    // killing form nnz
constexpr int NG_  = 128;     // graphs
constexpr int D2_  = 2 * D_;  // 496
constexpr int DP1_ = D_ + 1;  // 249

// ---------------- scratch (device globals; allocation is forbidden) ----------------
__device__ float g_t1[(size_t)N_ * HID_];    // node hidden (reused as nH)
__device__ float g_h[(size_t)N_ * D_];       // node features h
__device__ float g_eA[(size_t)E_ * D2_];     // edge MLP input [hs, br]
__device__ float g_eH[(size_t)E_ * HID_];    // edge hidden
__device__ float g_eM[(size_t)E_ * D_];      // edge messages
__device__ float g_agg[(size_t)N_ * D_];     // aggregated messages
__device__ float g_nA[(size_t)N_ * D2_];     // node update MLP input [h, agg]
__device__ float g_pooled[NG_ * DP1_];
__device__ float g_cnt[NG_];

__device__ __forceinline__ float silu_f(float v) {
    return v / (1.0f + expf(-v));
}

// ---------------- generic fp32 GEMM: C = act(A@W + bias) (+ res) ----------------
// A: M x K row-major, W: K x N row-major, bias: N, res/C: M x N
constexpr int BM = 64, BN = 64, BK = 16, TM = 4, TN = 4;

__global__ __launch_bounds__(256) void gemm_bias_act(
    const float* __restrict__ A, const float* __restrict__ W,
    const float* __restrict__ bias, const float* __restrict__ res,
    float* __restrict__ C, int M, int N, int K, int act)
{
    __shared__ float As[BK][BM];
    __shared__ float Ws[BK][BN + 1];

    const int tid = threadIdx.x;          // 256 threads
    const int tx = tid & 15;              // 0..15 -> N direction
    const int ty = tid >> 4;              // 0..15 -> M direction
    const int row0 = blockIdx.y * BM;
    const int col0 = blockIdx.x * BN;

    float acc[TM][TN];
    #pragma unroll
    for (int i = 0; i < TM; i++)
        #pragma unroll
        for (int j = 0; j < TN; j++) acc[i][j] = 0.0f;

    for (int k0 = 0; k0 < K; k0 += BK) {
        // load A tile (BM x BK)
        #pragma unroll
        for (int i = tid; i < BM * BK; i += 256) {
            int m = i / BK, k = i % BK;
            int gm = row0 + m, gk = k0 + k;
            As[k][m] = (gm < M && gk < K) ? __ldg(&A[(size_t)gm * K + gk]) : 0.0f;
        }
        // load W tile (BK x BN)
        #pragma unroll
        for (int i = tid; i < BK * BN; i += 256) {
            int k = i / BN, n = i % BN;
            int gk = k0 + k, gn = col0 + n;
            Ws[k][n] = (gk < K && gn < N) ? __ldg(&W[(size_t)gk * N + gn]) : 0.0f;
        }
        __syncthreads();

        #pragma unroll
        for (int k = 0; k < BK; k++) {
            float a[TM], b[TN];
            #pragma unroll
            for (int i = 0; i < TM; i++) a[i] = As[k][ty * TM + i];
            #pragma unroll
            for (int j = 0; j < TN; j++) b[j] = Ws[k][tx * TN + j];
            #pragma unroll
            for (int i = 0; i < TM; i++)
                #pragma unroll
                for (int j = 0; j < TN; j++) acc[i][j] = fmaf(a[i], b[j], acc[i][j]);
        }
        __syncthreads();
    }

    #pragma unroll
    for (int i = 0; i < TM; i++) {
        int gm = row0 + ty * TM + i;
        if (gm >= M) continue;
        #pragma unroll
        for (int j = 0; j < TN; j++) {
            int gn = col0 + tx * TN + j;
            if (gn >= N) continue;
            float v = acc[i][j] + __ldg(&bias[gn]);
            if (act) v = silu_f(v);
            if (res) v += res[(size_t)gm * N + gn];
            C[(size_t)gm * N + gn] = v;
        }
    }
}

// ---------------- edge gather + Lie bracket -> eA = [h[src], br] ----------------
__global__ __launch_bounds__(128) void edge_bracket_kernel(
    const float* __restrict__ h, const int* __restrict__ ei,
    const int* __restrict__ sci, const int* __restrict__ scj,
    const int* __restrict__ sck, const float* __restrict__ scc,
    float* __restrict__ eA)
{
    const int e = blockIdx.x;
    const int s = __ldg(&ei[e]);
    const int d = __ldg(&ei[E_ + e]);

    __shared__ float hs[D_], hd[D_], br[D_];
    for (int k = threadIdx.x; k < D_; k += 128) {
        hs[k] = __ldg(&h[(size_t)s * D_ + k]);
        hd[k] = __ldg(&h[(size_t)d * D_ + k]);
        br[k] = 0.0f;
    }
    __syncthreads();
    for (int t = threadIdx.x; t < NNZ_; t += 128) {
        float v = __ldg(&scc[t]) * hs[__ldg(&sci[t])] * hd[__ldg(&scj[t])];
        atomicAdd(&br[__ldg(&sck[t])], v);
    }
    __syncthreads();
    float* row = eA + (size_t)e * D2_;
    for (int k = threadIdx.x; k < D_; k += 128) {
        row[k]      = hs[k];
        row[D_ + k] = br[k];
    }
}

// ---------------- scatter-add edge messages to destination nodes ----------------
__global__ __launch_bounds__(256) void scatter_add_kernel(
    const float* __restrict__ eM, const int* __restrict__ dst,
    float* __restrict__ agg)
{
    const int e = blockIdx.x;
    const int d = __ldg(&dst[e]);
    const int k = threadIdx.x;
    if (k < D_) atomicAdd(&agg[(size_t)d * D_ + k], eM[(size_t)e * D_ + k]);
}

// ---------------- build node update input [h, agg] ----------------
__global__ void concat_kernel(const float* __restrict__ h,
                              const float* __restrict__ agg,
                              float* __restrict__ nA)
{
    size_t idx = (size_t)blockIdx.x * blockDim.x + threadIdx.x;
    if (idx >= (size_t)N_ * D2_) return;
    size_t n = idx / D2_;
    int k = (int)(idx - n * D2_);
    nA[idx] = (k < D_) ? h[n * D_ + k] : agg[n * D_ + (k - D_)];
}

__global__ void zero_kernel(float* __restrict__ p, size_t n) {
    size_t idx = (size_t)blockIdx.x * blockDim.x + threadIdx.x;
    if (idx < n) p[idx] = 0.0f;
}

// ---------------- killing form + pooling (scatter to graphs) ----------------
__global__ __launch_bounds__(128) void killing_pool_kernel(
    const float* __restrict__ h, const int* __restrict__ batch,
    const int* __restrict__ kbr, const int* __restrict__ kbc,
    const float* __restrict__ kbv,
    float* __restrict__ pooled, float* __restrict__ cnt)
{
    const int n = blockIdx.x;
    __shared__ float hrow[D_];
    __shared__ float wsum[4];
    for (int k = threadIdx.x; k < D_; k += 128)
        hrow[k] = h[(size_t)n * D_ + k];
    __syncthreads();

    float s = 0.0f;
    for (int t = threadIdx.x; t < NB_; t += 128)
        s += __ldg(&kbv[t]) * hrow[__ldg(&kbr[t])] * hrow[__ldg(&kbc[t])];
    // warp reduce
    #pragma unroll
    for (int off = 16; off > 0; off >>= 1)
        s += __shfl_down_sync(0xffffffffu, s, off);
    if ((threadIdx.x & 31) == 0) wsum[threadIdx.x >> 5] = s;
    __syncthreads();

    const int b = __ldg(&batch[n]);
    for (int k = threadIdx.x; k < D_; k += 128)
        atomicAdd(&pooled[b * DP1_ + k], hrow[k]);
    if (threadIdx.x == 0) {
        float ks = wsum[0] + wsum[1] + wsum[2] + wsum[3];
        atomicAdd(&pooled[b * DP1_ + D_], ks);
        atomicAdd(&cnt[b], 1.0f);
    }
}

// ---------------- final MLP per graph ----------------
__global__ __launch_bounds__(256) void final_mlp_kernel(
    const float* __restrict__ pooled, const float* __restrict__ cnt,
    const float* __restrict__ Wo1, const float* __restrict__ bo1,
    const float* __restrict__ Wo2, const float* __restrict__ bo2,
    float* __restrict__ out)
{
    const int g = blockIdx.x;
    __shared__ float p[DP1_];
    __shared__ float hid[HID_];
    const float c = fmaxf(cnt[g], 1.0f);
    for (int k = threadIdx.x; k < DP1_; k += 256)
        p[k] = pooled[g * DP1_ + k] / c;
    __syncthreads();

    const int j = threadIdx.x;  // one hidden unit per thread (HID_=256)
    float s = __ldg(&bo1[j]);
    for (int k = 0; k < DP1_; k++)
        s = fmaf(p[k], __ldg(&Wo1[k * HID_ + j]), s);
    hid[j] = silu_f(s);
    __syncthreads();

    if (j < OUT_) {
        float o = __ldg(&bo2[j]);
        for (int k = 0; k < HID_; k++)
            o = fmaf(hid[k], __ldg(&Wo2[k * OUT_ + j]), o);
        out[g * OUT_ + j] = o;
    }
}

// ---------------- host driver ----------------
static inline dim3 gemm_grid(int M, int N) {
    return dim3((N + BN - 1) / BN, (M + BM - 1) / BM);
}

extern "C" void kernel_launch(void* const* d_in, const int* in_sizes, int n_in,
                              void* d_out, int out_size)
{
    const float* x     = (const float*)d_in[0];
    const int*   ei    = (const int*)  d_in[1];
    const int*   batch = (const int*)  d_in[2];
    const int*   sci   = (const int*)  d_in[3];
    const int*   scj   = (const int*)  d_in[4];
    const int*   sck   = (const int*)  d_in[5];
    const float* scc   = (const float*)d_in[6];
    const int*   kbr   = (const int*)  d_in[7];
    const int*   kbc   = (const int*)  d_in[8];
    const float* kbv   = (const float*)d_in[9];
    const float* Wi1   = (const float*)d_in[10];
    const float* bi1   = (const float*)d_in[11];
    const float* Wi2   = (const float*)d_in[12];
    const float* bi2   = (const float*)d_in[13];
    const float* msgW1 = (const float*)d_in[14];
    const float* msgb1 = (const float*)d_in[15];
    const float* msgW2 = (const float*)d_in[16];
    const float* msgb2 = (const float*)d_in[17];
    const float* updW1 = (const float*)d_in[18];
    const float* updb1 = (const float*)d_in[19];
    const float* updW2 = (const float*)d_in[20];
    const float* updb2 = (const float*)d_in[21];
    const float* Wo1   = (const float*)d_in[22];
    const float* bo1   = (const float*)d_in[23];
    const float* Wo2   = (const float*)d_in[24];
    const float* bo2   = (const float*)d_in[25];

    float *t1, *h, *eA, *eH, *eM, *agg, *nA, *pooled, *cnt;
    cudaGetSymbolAddress((void**)&t1,     g_t1);
    cudaGetSymbolAddress((void**)&h,      g_h);
    cudaGetSymbolAddress((void**)&eA,     g_eA);
    cudaGetSymbolAddress((void**)&eH,     g_eH);
    cudaGetSymbolAddress((void**)&eM,     g_eM);
    cudaGetSymbolAddress((void**)&agg,    g_agg);
    cudaGetSymbolAddress((void**)&nA,     g_nA);
    cudaGetSymbolAddress((void**)&pooled, g_pooled);
    cudaGetSymbolAddress((void**)&cnt,    g_cnt);

    // ---- input MLP: h = silu(x@Wi1+b)@Wi2+b ----
    gemm_bias_act<<<gemm_grid(N_, HID_), 256>>>(x,  Wi1, bi1, nullptr, t1, N_, HID_, IN_,  1);
    gemm_bias_act<<<gemm_grid(N_, D_),   256>>>(t1, Wi2, bi2, nullptr, h,  N_, D_,   HID_, 0);

    // ---- message passing layers ----
    for (int l = 0; l < NL_; l++) {
        const float* mW1 = msgW1 + (size_t)l * D2_ * HID_;
        const float* mb1 = msgb1 + (size_t)l * HID_;
        const float* mW2 = msgW2 + (size_t)l * HID_ * D_;
        const float* mb2 = msgb2 + (size_t)l * D_;
        const float* uW1 = updW1 + (size_t)l * D2_ * HID_;
        const float* ub1 = updb1 + (size_t)l * HID_;
        const float* uW2 = updW2 + (size_t)l * HID_ * D_;
        const float* ub2 = updb2 + (size_t)l * D_;

        edge_bracket_kernel<<<E_, 128>>>(h, ei, sci, scj, sck, scc, eA);
        gemm_bias_act<<<gemm_grid(E_, HID_), 256>>>(eA, mW1, mb1, nullptr, eH, E_, HID_, D2_,  1);
        gemm_bias_act<<<gemm_grid(E_, D_),   256>>>(eH, mW2, mb2, nullptr, eM, E_, D_,   HID_, 0);

        {
            size_t n = (size_t)N_ * D_;
            zero_kernel<<<(unsigned)((n + 255) / 256), 256>>>(agg, n);
        }
        scatter_add_kernel<<<E_, 256>>>(eM, ei + E_, agg);

        {
            size_t n = (size_t)N_ * D2_;
            concat_kernel<<<(unsigned)((n + 255) / 256), 256>>>(h, agg, nA);
        }
        gemm_bias_act<<<gemm_grid(N_, HID_), 256>>>(nA, uW1, ub1, nullptr, t1, N_, HID_, D2_,  1);
        gemm_bias_act<<<gemm_grid(N_, D_),   256>>>(t1, uW2, ub2, h,       h,  N_, D_,   HID_, 0);
    }

    // ---- killing form + pooling ----
    {
        size_t n = NG_ * DP1_;
        zero_kernel<<<(unsigned)((n + 255) / 256), 256>>>(pooled, n);
        zero_kernel<<<1, NG_>>>(cnt, NG_);
    }
    killing_pool_kernel<<<N_, 128>>>(h, batch, kbr, kbc, kbv, pooled, cnt);

    // ---- final MLP ----
    final_mlp_kernel<<<NG_, 256>>>(pooled, cnt, Wo1, bo1, Wo2, bo2, (float*)d_out);
}

// round 2
// speedup vs baseline: 1.6963x; 1.6963x over previous
#include <cuda_runtime.h>
#include <cuda_bf16.h>
#include <math.h>

// ---------------- problem constants ----------------
constexpr int N_   = 20000;   // nodes
constexpr int E_   = 100000;  // edges
constexpr int D_   = 248;     // Lie algebra dim
constexpr int HID_ = 256;     // MLP hidden
constexpr int IN_  = 128;     // input feature dim
constexpr int OUT_ = 16;      // output dim
constexpr int NL_  = 4;       // layers
constexpr int NNZ_ = 512;     // structure constant nnz
constexpr int NB_  = 1024;    // killing form nnz
constexpr int NG_  = 128;     // graphs
constexpr int D2_  = 2 * D_;  // 496
constexpr int DP1_ = D_ + 1;  // 249

// ---------------- scratch (device globals; allocation is forbidden) ----------------
__device__ float g_t1[(size_t)N_ * HID_];    // node hidden
__device__ float g_h[(size_t)N_ * D_];       // node features h
__device__ float g_eA[(size_t)E_ * D2_];     // edge MLP input [hs, br]
__device__ float g_eH[(size_t)E_ * HID_];    // edge hidden
__device__ float g_eM[(size_t)E_ * D_];      // edge messages
__device__ float g_agg[(size_t)N_ * D_];     // aggregated messages
__device__ float g_nA[(size_t)N_ * D2_];     // node update MLP input [h, agg]
__device__ float g_pooled[NG_ * DP1_];
__device__ float g_cnt[NG_];

__device__ __forceinline__ float silu_f(float v) {
    return v / (1.0f + expf(-v));
}

// ---------------- fp32 SGEMM: C = act(A@W + bias) (+ res) ----------------
// A: M x K row-major, W: K x N row-major, bias: N, res/C: M x N
// Requires K % 8 == 0, N % 4 == 0 (holds for all call sites: K in {128,256,496}, N in {248,256}).
constexpr int BM = 128, BN = 128, BK = 8;

__global__ __launch_bounds__(256) void sgemm_bias_act(
    const float* __restrict__ A, const float* __restrict__ W,
    const float* __restrict__ bias, const float* __restrict__ res,
    float* __restrict__ C, int M, int N, int K, int act)
{
    __shared__ float As[BK][BM];
    __shared__ float Bs[BK][BN];

    const int tid  = threadIdx.x;
    const int row0 = blockIdx.y * BM;
    const int col0 = blockIdx.x * BN;

    // A tile load mapping: one float4 along K per thread
    const int a_row = tid >> 1;          // 0..127
    const int a_k   = (tid & 1) * 4;     // 0 or 4
    // W tile load mapping: one float4 along N per thread
    const int b_k   = tid >> 5;          // 0..7
    const int b_col = (tid & 31) * 4;    // 0..124
    // compute mapping: 8x8 microtile
    const int tx = tid & 15;             // col group
    const int ty = tid >> 4;             // row group

    const int gmA = row0 + a_row;
    const bool aValid = (gmA < M);
    const int gnB = col0 + b_col;
    const bool bValid = (gnB + 3 < N);

    float acc[8][8];
    #pragma unroll
    for (int i = 0; i < 8; i++)
        #pragma unroll
        for (int j = 0; j < 8; j++) acc[i][j] = 0.0f;

    float4 aReg, bReg;

    // prefetch first tiles into registers
    {
        aReg = aValid ? *(const float4*)&A[(size_t)gmA * K + a_k]
                      : make_float4(0.f, 0.f, 0.f, 0.f);
        bReg = bValid ? *(const float4*)&W[(size_t)b_k * N + gnB]
                      : make_float4(0.f, 0.f, 0.f, 0.f);
    }

    for (int k0 = 0; k0 < K; k0 += BK) {
        // stage registers -> shared
        As[a_k + 0][a_row] = aReg.x;
        As[a_k + 1][a_row] = aReg.y;
        As[a_k + 2][a_row] = aReg.z;
        As[a_k + 3][a_row] = aReg.w;
        *(float4*)&Bs[b_k][b_col] = bReg;
        __syncthreads();

        // prefetch next tiles (overlaps with compute below)
        if (k0 + BK < K) {
            const int kn = k0 + BK;
            aReg = aValid ? *(const float4*)&A[(size_t)gmA * K + kn + a_k]
                          : make_float4(0.f, 0.f, 0.f, 0.f);
            bReg = bValid ? *(const float4*)&W[(size_t)(kn + b_k) * N + gnB]
                          : make_float4(0.f, 0.f, 0.f, 0.f);
        }

        #pragma unroll
        for (int k = 0; k < BK; k++) {
            float a[8], b[8];
            *(float4*)&a[0] = *(const float4*)&As[k][ty * 8];
            *(float4*)&a[4] = *(const float4*)&As[k][ty * 8 + 4];
            *(float4*)&b[0] = *(const float4*)&Bs[k][tx * 8];
            *(float4*)&b[4] = *(const float4*)&Bs[k][tx * 8 + 4];
            #pragma unroll
            for (int i = 0; i < 8; i++)
                #pragma unroll
                for (int j = 0; j < 8; j++)
                    acc[i][j] = fmaf(a[i], b[j], acc[i][j]);
        }
        __syncthreads();
    }

    // epilogue: bias + activation (+ residual), guarded stores
    #pragma unroll
    for (int i = 0; i < 8; i++) {
        const int gm = row0 + ty * 8 + i;
        if (gm >= M) continue;
        #pragma unroll
        for (int j = 0; j < 8; j++) {
            const int gn = col0 + tx * 8 + j;
            if (gn >= N) continue;
            float v = acc[i][j] + __ldg(&bias[gn]);
            if (act) v = silu_f(v);
            if (res) v += res[(size_t)gm * N + gn];
            C[(size_t)gm * N + gn] = v;
        }
    }
}

// ---------------- edge gather + Lie bracket -> eA = [h[src], br] ----------------
__global__ __launch_bounds__(128) void edge_bracket_kernel(
    const float* __restrict__ h, const int* __restrict__ ei,
    const int* __restrict__ sci, const int* __restrict__ scj,
    const int* __restrict__ sck, const float* __restrict__ scc,
    float* __restrict__ eA)
{
    const int e = blockIdx.x;
    const int s = __ldg(&ei[e]);
    const int d = __ldg(&ei[E_ + e]);

    __shared__ float hs[D_], hd[D_], br[D_];
    for (int k = threadIdx.x; k < D_; k += 128) {
        hs[k] = __ldg(&h[(size_t)s * D_ + k]);
        hd[k] = __ldg(&h[(size_t)d * D_ + k]);
        br[k] = 0.0f;
    }
    __syncthreads();
    for (int t = threadIdx.x; t < NNZ_; t += 128) {
        float v = __ldg(&scc[t]) * hs[__ldg(&sci[t])] * hd[__ldg(&scj[t])];
        atomicAdd(&br[__ldg(&sck[t])], v);
    }
    __syncthreads();
    float* row = eA + (size_t)e * D2_;
    for (int k = threadIdx.x; k < D_; k += 128) {
        row[k]      = hs[k];
        row[D_ + k] = br[k];
    }
}

// ---------------- scatter-add edge messages to destination nodes ----------------
__global__ __launch_bounds__(256) void scatter_add_kernel(
    const float* __restrict__ eM, const int* __restrict__ dst,
    float* __restrict__ agg)
{
    const int e = blockIdx.x;
    const int d = __ldg(&dst[e]);
    const int k = threadIdx.x;
    if (k < D_) atomicAdd(&agg[(size_t)d * D_ + k], eM[(size_t)e * D_ + k]);
}

// ---------------- build node update input [h, agg] ----------------
__global__ void concat_kernel(const float* __restrict__ h,
                              const float* __restrict__ agg,
                              float* __restrict__ nA)
{
    size_t idx = (size_t)blockIdx.x * blockDim.x + threadIdx.x;
    if (idx >= (size_t)N_ * D2_) return;
    size_t n = idx / D2_;
    int k = (int)(idx - n * D2_);
    nA[idx] = (k < D_) ? h[n * D_ + k] : agg[n * D_ + (k - D_)];
}

__global__ void zero_kernel(float* __restrict__ p, size_t n) {
    size_t idx = (size_t)blockIdx.x * blockDim.x + threadIdx.x;
    if (idx < n) p[idx] = 0.0f;
}

// ---------------- killing form + pooling (scatter to graphs) ----------------
__global__ __launch_bounds__(128) void killing_pool_kernel(
    const float* __restrict__ h, const int* __restrict__ batch,
    const int* __restrict__ kbr, const int* __restrict__ kbc,
    const float* __restrict__ kbv,
    float* __restrict__ pooled, float* __restrict__ cnt)
{
    const int n = blockIdx.x;
    __shared__ float hrow[D_];
    __shared__ float wsum[4];
    for (int k = threadIdx.x; k < D_; k += 128)
        hrow[k] = h[(size_t)n * D_ + k];
    __syncthreads();

    float s = 0.0f;
    for (int t = threadIdx.x; t < NB_; t += 128)
        s += __ldg(&kbv[t]) * hrow[__ldg(&kbr[t])] * hrow[__ldg(&kbc[t])];
    #pragma unroll
    for (int off = 16; off > 0; off >>= 1)
        s += __shfl_down_sync(0xffffffffu, s, off);
    if ((threadIdx.x & 31) == 0) wsum[threadIdx.x >> 5] = s;
    __syncthreads();

    const int b = __ldg(&batch[n]);
    for (int k = threadIdx.x; k < D_; k += 128)
        atomicAdd(&pooled[b * DP1_ + k], hrow[k]);
    if (threadIdx.x == 0) {
        float ks = wsum[0] + wsum[1] + wsum[2] + wsum[3];
        atomicAdd(&pooled[b * DP1_ + D_], ks);
        atomicAdd(&cnt[b], 1.0f);
    }
}

// ---------------- final MLP per graph ----------------
__global__ __launch_bounds__(256) void final_mlp_kernel(
    const float* __restrict__ pooled, const float* __restrict__ cnt,
    const float* __restrict__ Wo1, const float* __restrict__ bo1,
    const float* __restrict__ Wo2, const float* __restrict__ bo2,
    float* __restrict__ out)
{
    const int g = blockIdx.x;
    __shared__ float p[DP1_];
    __shared__ float hid[HID_];
    const float c = fmaxf(cnt[g], 1.0f);
    for (int k = threadIdx.x; k < DP1_; k += 256)
        p[k] = pooled[g * DP1_ + k] / c;
    __syncthreads();

    const int j = threadIdx.x;  // one hidden unit per thread (HID_=256)
    float s = __ldg(&bo1[j]);
    for (int k = 0; k < DP1_; k++)
        s = fmaf(p[k], __ldg(&Wo1[k * HID_ + j]), s);
    hid[j] = silu_f(s);
    __syncthreads();

    if (j < OUT_) {
        float o = __ldg(&bo2[j]);
        for (int k = 0; k < HID_; k++)
            o = fmaf(hid[k], __ldg(&Wo2[k * OUT_ + j]), o);
        out[g * OUT_ + j] = o;
    }
}

// ---------------- host driver ----------------
static inline dim3 sgemm_grid(int M, int N) {
    return dim3((N + BN - 1) / BN, (M + BM - 1) / BM);
}

extern "C" void kernel_launch(void* const* d_in, const int* in_sizes, int n_in,
                              void* d_out, int out_size)
{
    const float* x     = (const float*)d_in[0];
    const int*   ei    = (const int*)  d_in[1];
    const int*   batch = (const int*)  d_in[2];
    const int*   sci   = (const int*)  d_in[3];
    const int*   scj   = (const int*)  d_in[4];
    const int*   sck   = (const int*)  d_in[5];
    const float* scc   = (const float*)d_in[6];
    const int*   kbr   = (const int*)  d_in[7];
    const int*   kbc   = (const int*)  d_in[8];
    const float* kbv   = (const float*)d_in[9];
    const float* Wi1   = (const float*)d_in[10];
    const float* bi1   = (const float*)d_in[11];
    const float* Wi2   = (const float*)d_in[12];
    const float* bi2   = (const float*)d_in[13];
    const float* msgW1 = (const float*)d_in[14];
    const float* msgb1 = (const float*)d_in[15];
    const float* msgW2 = (const float*)d_in[16];
    const float* msgb2 = (const float*)d_in[17];
    const float* updW1 = (const float*)d_in[18];
    const float* updb1 = (const float*)d_in[19];
    const float* updW2 = (const float*)d_in[20];
    const float* updb2 = (const float*)d_in[21];
    const float* Wo1   = (const float*)d_in[22];
    const float* bo1   = (const float*)d_in[23];
    const float* Wo2   = (const float*)d_in[24];
    const float* bo2   = (const float*)d_in[25];

    float *t1, *h, *eA, *eH, *eM, *agg, *nA, *pooled, *cnt;
    cudaGetSymbolAddress((void**)&t1,     g_t1);
    cudaGetSymbolAddress((void**)&h,      g_h);
    cudaGetSymbolAddress((void**)&eA,     g_eA);
    cudaGetSymbolAddress((void**)&eH,     g_eH);
    cudaGetSymbolAddress((void**)&eM,     g_eM);
    cudaGetSymbolAddress((void**)&agg,    g_agg);
    cudaGetSymbolAddress((void**)&nA,     g_nA);
    cudaGetSymbolAddress((void**)&pooled, g_pooled);
    cudaGetSymbolAddress((void**)&cnt,    g_cnt);

    // ---- input MLP: h = silu(x@Wi1+b)@Wi2+b ----
    sgemm_bias_act<<<sgemm_grid(N_, HID_), 256>>>(x,  Wi1, bi1, nullptr, t1, N_, HID_, IN_,  1);
    sgemm_bias_act<<<sgemm_grid(N_, D_),   256>>>(t1, Wi2, bi2, nullptr, h,  N_, D_,   HID_, 0);

    // ---- message passing layers ----
    for (int l = 0; l < NL_; l++) {
        const float* mW1 = msgW1 + (size_t)l * D2_ * HID_;
        const float* mb1 = msgb1 + (size_t)l * HID_;
        const float* mW2 = msgW2 + (size_t)l * HID_ * D_;
        const float* mb2 = msgb2 + (size_t)l * D_;
        const float* uW1 = updW1 + (size_t)l * D2_ * HID_;
        const float* ub1 = updb1 + (size_t)l * HID_;
        const float* uW2 = updW2 + (size_t)l * HID_ * D_;
        const float* ub2 = updb2 + (size_t)l * D_;

        edge_bracket_kernel<<<E_, 128>>>(h, ei, sci, scj, sck, scc, eA);
        sgemm_bias_act<<<sgemm_grid(E_, HID_), 256>>>(eA, mW1, mb1, nullptr, eH, E_, HID_, D2_,  1);
        sgemm_bias_act<<<sgemm_grid(E_, D_),   256>>>(eH, mW2, mb2, nullptr, eM, E_, D_,   HID_, 0);

        {
            size_t n = (size_t)N_ * D_;
            zero_kernel<<<(unsigned)((n + 255) / 256), 256>>>(agg, n);
        }
        scatter_add_kernel<<<E_, 256>>>(eM, ei + E_, agg);

        {
            size_t n = (size_t)N_ * D2_;
            concat_kernel<<<(unsigned)((n + 255) / 256), 256>>>(h, agg, nA);
        }
        sgemm_bias_act<<<sgemm_grid(N_, HID_), 256>>>(nA, uW1, ub1, nullptr, t1, N_, HID_, D2_,  1);
        sgemm_bias_act<<<sgemm_grid(N_, D_),   256>>>(t1, uW2, ub2, h,       h,  N_, D_,   HID_, 0);
    }

    // ---- killing form + pooling ----
    {
        size_t n = NG_ * DP1_;
        zero_kernel<<<(unsigned)((n + 255) / 256), 256>>>(pooled, n);
        zero_kernel<<<1, NG_>>>(cnt, NG_);
    }
    killing_pool_kernel<<<N_, 128>>>(h, batch, kbr, kbc, kbv, pooled, cnt);

    // ---- final MLP ----
    final_mlp_kernel<<<NG_, 256>>>(pooled, cnt, Wo1, bo1, Wo2, bo2, (float*)d_out);
}

// round 4
// speedup vs baseline: 2.2448x; 1.3234x over previous
#include <cuda_runtime.h>
#include <cuda_bf16.h>
#include <math.h>
#include <stdint.h>

// ---------------- problem constants ----------------
constexpr int N_   = 20000;   // nodes
constexpr int E_   = 100000;  // edges
constexpr int D_   = 248;     // Lie algebra dim
constexpr int HID_ = 256;     // MLP hidden
constexpr int IN_  = 128;     // input feature dim
constexpr int OUT_ = 16;      // output dim
constexpr int NL_  = 4;       // layers
constexpr int NNZ_ = 512;     // structure constant nnz
constexpr int NB_  = 1024;    // killing form nnz
constexpr int NG_  = 128;     // graphs
constexpr int D2_  = 2 * D_;  // 496
constexpr int DP1_ = D_ + 1;  // 249

// ---------------- scratch (device globals; allocation is forbidden) ----------------
__device__ float g_t1[(size_t)N_ * HID_];    // node hidden
__device__ float g_h[(size_t)N_ * D_];       // node features h
__device__ float g_br[(size_t)E_ * D_];      // per-edge Lie bracket
__device__ float g_eH[(size_t)E_ * HID_];    // edge hidden
__device__ float g_eM[(size_t)E_ * D_];      // edge messages
__device__ float g_agg[(size_t)N_ * D_];     // aggregated messages
__device__ float g_pooled[NG_ * DP1_];
__device__ float g_cnt[NG_];

__device__ __forceinline__ float silu_f(float v) {
    return v / (1.0f + expf(-v));
}

__device__ __forceinline__ float to_tf32(float x) {
    uint32_t u;
    asm("cvt.rna.tf32.f32 %0, %1;" : "=r"(u) : "f"(x));
    return __uint_as_float(u);
}

// ---------------- 3xTF32 tensor-core GEMM with split-K A operand ----------------
// C = act(A @ W + bias) (+ res), fp32-grade accuracy via hi/lo TF32 decomposition:
//   x = hi + lo (hi = tf32(x), lo = tf32(x - hi));  A@W ~= Ah@Wh + Ah@Wl + Al@Wh
// A operand columns [0, K1)  come from A1 (row gathered via gidx if non-null, stride K1)
// A operand columns [K1, K)  come from A2 (direct row, stride K-K1)
// W: K x N row-major. Requires K % 16 == 0, K1 % 4 == 0, N % 4 == 0.
constexpr int BM = 128, BN = 128, BK = 16;

__global__ __launch_bounds__(256) void gemm_3xtf32(
    const float* __restrict__ A1, const int* __restrict__ gidx,
    const float* __restrict__ A2, int K1,
    const float* __restrict__ W, const float* __restrict__ bias,
    const float* __restrict__ res, float* __restrict__ C,
    int M, int N, int K, int act)
{
    __shared__ float AsH[BM][BK + 4];   // stride 20: conflict-free frag loads
    __shared__ float AsL[BM][BK + 4];
    __shared__ float WsH[BK][BN + 8];   // stride 136: conflict-free frag loads
    __shared__ float WsL[BK][BN + 8];

    const int tid  = threadIdx.x;
    const int lane = tid & 31;
    const int wid  = tid >> 5;
    const int row0 = blockIdx.y * BM;
    const int col0 = blockIdx.x * BN;

    // ---- global load mappings (2 float4 per thread per operand) ----
    const int aRow0 = tid >> 2;             // 0..63
    const int aRow1 = aRow0 + 64;           // 64..127
    const int aKq   = (tid & 3) * 4;        // 0,4,8,12
    const int wK0   = tid >> 5;             // 0..7
    const int wK1   = wK0 + 8;              // 8..15
    const int wCol  = (tid & 31) * 4;       // 0..124

    const int K2s = K - K1;                 // stride of A2

    // resolve (possibly gathered) A1 rows once
    const int gRow0 = row0 + aRow0;
    const int gRow1 = row0 + aRow1;
    const bool av0 = gRow0 < M;
    const bool av1 = gRow1 < M;
    size_t a1off0 = 0, a1off1 = 0, a2off0 = 0, a2off1 = 0;
    if (av0) {
        int r = gidx ? __ldg(&gidx[gRow0]) : gRow0;
        a1off0 = (size_t)r * K1;
        a2off0 = (size_t)gRow0 * K2s;
    }
    if (av1) {
        int r = gidx ? __ldg(&gidx[gRow1]) : gRow1;
        a1off1 = (size_t)r * K1;
        a2off1 = (size_t)gRow1 * K2s;
    }
    const int gnW = col0 + wCol;
    const bool wv = gnW < N;                // N%4==0 so covers the float4

    // warp tile: 32 (m) x 64 (n); warps 4x2
    const int wm = (wid & 3) * 32;
    const int wn = (wid >> 2) * 64;
    const int grp = lane >> 2;
    const int qid = lane & 3;

    float acc[2][8][4];
    #pragma unroll
    for (int mt = 0; mt < 2; mt++)
        #pragma unroll
        for (int nt = 0; nt < 8; nt++)
            #pragma unroll
            for (int c = 0; c < 4; c++) acc[mt][nt][c] = 0.0f;

    float4 aR0, aR1, wR0, wR1;

    auto loadA = [&](int k0, int kq, size_t o1, size_t o2, bool valid) -> float4 {
        if (!valid) return make_float4(0.f, 0.f, 0.f, 0.f);
        int kg = k0 + kq;
        if (kg < K1) return *(const float4*)&A1[o1 + kg];
        return *(const float4*)&A2[o2 + (kg - K1)];
    };
    auto loadW = [&](int k0, int kr) -> float4 {
        if (!wv) return make_float4(0.f, 0.f, 0.f, 0.f);
        return *(const float4*)&W[(size_t)(k0 + kr) * N + gnW];
    };

    aR0 = loadA(0, aKq, a1off0, a2off0, av0);
    aR1 = loadA(0, aKq, a1off1, a2off1, av1);
    wR0 = loadW(0, wK0);
    wR1 = loadW(0, wK1);

    // hi/lo split helper: stages a float4 into hi/lo smem slots
    auto stageA = [&](int r, int kq, float4 v) {
        float h0 = to_tf32(v.x), h1 = to_tf32(v.y), h2 = to_tf32(v.z), h3 = to_tf32(v.w);
        *(float4*)&AsH[r][kq] = make_float4(h0, h1, h2, h3);
        *(float4*)&AsL[r][kq] = make_float4(to_tf32(v.x - h0), to_tf32(v.y - h1),
                                            to_tf32(v.z - h2), to_tf32(v.w - h3));
    };
    auto stageW = [&](int kr, int cc, float4 v) {
        float h0 = to_tf32(v.x), h1 = to_tf32(v.y), h2 = to_tf32(v.z), h3 = to_tf32(v.w);
        *(float4*)&WsH[kr][cc] = make_float4(h0, h1, h2, h3);
        *(float4*)&WsL[kr][cc] = make_float4(to_tf32(v.x - h0), to_tf32(v.y - h1),
                                             to_tf32(v.z - h2), to_tf32(v.w - h3));
    };

    for (int k0 = 0; k0 < K; k0 += BK) {
        stageA(aRow0, aKq, aR0);
        stageA(aRow1, aKq, aR1);
        stageW(wK0, wCol, wR0);
        stageW(wK1, wCol, wR1);
        __syncthreads();

        if (k0 + BK < K) {
            const int kn = k0 + BK;
            aR0 = loadA(kn, aKq, a1off0, a2off0, av0);
            aR1 = loadA(kn, aKq, a1off1, a2off1, av1);
            wR0 = loadW(kn, wK0);
            wR1 = loadW(kn, wK1);
        }

        #pragma unroll
        for (int kk = 0; kk < BK; kk += 8) {
            uint32_t ah[2][4], al[2][4];
            #pragma unroll
            for (int mt = 0; mt < 2; mt++) {
                const int ar = wm + 16 * mt + grp;
                ah[mt][0] = __float_as_uint(AsH[ar    ][kk + qid]);
                ah[mt][1] = __float_as_uint(AsH[ar + 8][kk + qid]);
                ah[mt][2] = __float_as_uint(AsH[ar    ][kk + qid + 4]);
                ah[mt][3] = __float_as_uint(AsH[ar + 8][kk + qid + 4]);
                al[mt][0] = __float_as_uint(AsL[ar    ][kk + qid]);
                al[mt][1] = __float_as_uint(AsL[ar + 8][kk + qid]);
                al[mt][2] = __float_as_uint(AsL[ar    ][kk + qid + 4]);
                al[mt][3] = __float_as_uint(AsL[ar + 8][kk + qid + 4]);
            }
            #pragma unroll
            for (int nt = 0; nt < 8; nt++) {
                const int bc = wn + 8 * nt + grp;
                uint32_t bh0 = __float_as_uint(WsH[kk + qid    ][bc]);
                uint32_t bh1 = __float_as_uint(WsH[kk + qid + 4][bc]);
                uint32_t bl0 = __float_as_uint(WsL[kk + qid    ][bc]);
                uint32_t bl1 = __float_as_uint(WsL[kk + qid + 4][bc]);
                #pragma unroll
                for (int mt = 0; mt < 2; mt++) {
                    #define MMA_TF32(Afr, B0, B1)                                          \
                        asm volatile(                                                      \
                            "mma.sync.aligned.m16n8k8.row.col.f32.tf32.tf32.f32 "          \
                            "{%0,%1,%2,%3}, {%4,%5,%6,%7}, {%8,%9}, {%0,%1,%2,%3};"        \
                            : "+f"(acc[mt][nt][0]), "+f"(acc[mt][nt][1]),                  \
                              "+f"(acc[mt][nt][2]), "+f"(acc[mt][nt][3])                   \
                            : "r"(Afr[mt][0]), "r"(Afr[mt][1]),                            \
                              "r"(Afr[mt][2]), "r"(Afr[mt][3]),                            \
                              "r"(B0), "r"(B1))
                    MMA_TF32(ah, bh0, bh1);   // hi * hi
                    MMA_TF32(al, bh0, bh1);   // lo * hi
                    MMA_TF32(ah, bl0, bl1);   // hi * lo
                    #undef MMA_TF32
                }
            }
        }
        __syncthreads();
    }

    // ---- epilogue: bias + activation (+ residual), float2 stores ----
    #pragma unroll
    for (int mt = 0; mt < 2; mt++) {
        #pragma unroll
        for (int rr = 0; rr < 2; rr++) {
            const int gm = row0 + wm + 16 * mt + grp + rr * 8;
            if (gm >= M) continue;
            #pragma unroll
            for (int nt = 0; nt < 8; nt++) {
                const int gn = col0 + wn + 8 * nt + qid * 2;
                if (gn >= N) continue;   // N even, pair aligned
                float2 bb = __ldg((const float2*)&bias[gn]);
                float v0 = acc[mt][nt][rr * 2 + 0] + bb.x;
                float v1 = acc[mt][nt][rr * 2 + 1] + bb.y;
                if (act) { v0 = silu_f(v0); v1 = silu_f(v1); }
                if (res) {
                    float2 rv = *(const float2*)&res[(size_t)gm * N + gn];
                    v0 += rv.x; v1 += rv.y;
                }
                *(float2*)&C[(size_t)gm * N + gn] = make_float2(v0, v1);
            }
        }
    }
}

// ---------------- edge gather + Lie bracket -> br ----------------
__global__ __launch_bounds__(128) void edge_bracket_kernel(
    const float* __restrict__ h, const int* __restrict__ ei,
    const int* __restrict__ sci, const int* __restrict__ scj,
    const int* __restrict__ sck, const float* __restrict__ scc,
    float* __restrict__ br)
{
    const int e = blockIdx.x;
    const int s = __ldg(&ei[e]);
    const int d = __ldg(&ei[E_ + e]);

    __shared__ float hs[D_], hd[D_], brs[D_];
    for (int k = threadIdx.x; k < D_; k += 128) {
        hs[k]  = __ldg(&h[(size_t)s * D_ + k]);
        hd[k]  = __ldg(&h[(size_t)d * D_ + k]);
        brs[k] = 0.0f;
    }
    __syncthreads();
    for (int t = threadIdx.x; t < NNZ_; t += 128) {
        float v = __ldg(&scc[t]) * hs[__ldg(&sci[t])] * hd[__ldg(&scj[t])];
        atomicAdd(&brs[__ldg(&sck[t])], v);
    }
    __syncthreads();
    float* row = br + (size_t)e * D_;
    for (int k = threadIdx.x; k < D_; k += 128)
        row[k] = brs[k];
}

// ---------------- scatter-add edge messages to destination nodes ----------------
__global__ __launch_bounds__(256) void scatter_add_kernel(
    const float* __restrict__ eM, const int* __restrict__ dst,
    float* __restrict__ agg)
{
    const int e = blockIdx.x;
    const int d = __ldg(&dst[e]);
    const int k = threadIdx.x;
    if (k < D_) atomicAdd(&agg[(size_t)d * D_ + k], eM[(size_t)e * D_ + k]);
}

__global__ void zero_kernel(float* __restrict__ p, size_t n) {
    size_t idx = (size_t)blockIdx.x * blockDim.x + threadIdx.x;
    if (idx < n) p[idx] = 0.0f;
}

// ---------------- killing form + pooling (scatter to graphs) ----------------
__global__ __launch_bounds__(128) void killing_pool_kernel(
    const float* __restrict__ h, const int* __restrict__ batch,
    const int* __restrict__ kbr, const int* __restrict__ kbc,
    const float* __restrict__ kbv,
    float* __restrict__ pooled, float* __restrict__ cnt)
{
    const int n = blockIdx.x;
    __shared__ float hrow[D_];
    __shared__ float wsum[4];
    for (int k = threadIdx.x; k < D_; k += 128)
        hrow[k] = h[(size_t)n * D_ + k];
    __syncthreads();

    float s = 0.0f;
    for (int t = threadIdx.x; t < NB_; t += 128)
        s += __ldg(&kbv[t]) * hrow[__ldg(&kbr[t])] * hrow[__ldg(&kbc[t])];
    #pragma unroll
    for (int off = 16; off > 0; off >>= 1)
        s += __shfl_down_sync(0xffffffffu, s, off);
    if ((threadIdx.x & 31) == 0) wsum[threadIdx.x >> 5] = s;
    __syncthreads();

    const int b = __ldg(&batch[n]);
    for (int k = threadIdx.x; k < D_; k += 128)
        atomicAdd(&pooled[b * DP1_ + k], hrow[k]);
    if (threadIdx.x == 0) {
        float ks = wsum[0] + wsum[1] + wsum[2] + wsum[3];
        atomicAdd(&pooled[b * DP1_ + D_], ks);
        atomicAdd(&cnt[b], 1.0f);
    }
}

// ---------------- final MLP per graph ----------------
__global__ __launch_bounds__(256) void final_mlp_kernel(
    const float* __restrict__ pooled, const float* __restrict__ cnt,
    const float* __restrict__ Wo1, const float* __restrict__ bo1,
    const float* __restrict__ Wo2, const float* __restrict__ bo2,
    float* __restrict__ out)
{
    const int g = blockIdx.x;
    __shared__ float p[DP1_];
    __shared__ float hid[HID_];
    const float c = fmaxf(cnt[g], 1.0f);
    for (int k = threadIdx.x; k < DP1_; k += 256)
        p[k] = pooled[g * DP1_ + k] / c;
    __syncthreads();

    const int j = threadIdx.x;
    float s = __ldg(&bo1[j]);
    for (int k = 0; k < DP1_; k++)
        s = fmaf(p[k], __ldg(&Wo1[k * HID_ + j]), s);
    hid[j] = silu_f(s);
    __syncthreads();

    if (j < OUT_) {
        float o = __ldg(&bo2[j]);
        for (int k = 0; k < HID_; k++)
            o = fmaf(hid[k], __ldg(&Wo2[k * OUT_ + j]), o);
        out[g * OUT_ + j] = o;
    }
}

// ---------------- host driver ----------------
static inline dim3 gemm_grid(int M, int N) {
    return dim3((N + BN - 1) / BN, (M + BM - 1) / BM);
}

extern "C" void kernel_launch(void* const* d_in, const int* in_sizes, int n_in,
                              void* d_out, int out_size)
{
    const float* x     = (const float*)d_in[0];
    const int*   ei    = (const int*)  d_in[1];
    const int*   batch = (const int*)  d_in[2];
    const int*   sci   = (const int*)  d_in[3];
    const int*   scj   = (const int*)  d_in[4];
    const int*   sck   = (const int*)  d_in[5];
    const float* scc   = (const float*)d_in[6];
    const int*   kbr   = (const int*)  d_in[7];
    const int*   kbc   = (const int*)  d_in[8];
    const float* kbv   = (const float*)d_in[9];
    const float* Wi1   = (const float*)d_in[10];
    const float* bi1   = (const float*)d_in[11];
    const float* Wi2   = (const float*)d_in[12];
    const float* bi2   = (const float*)d_in[13];
    const float* msgW1 = (const float*)d_in[14];
    const float* msgb1 = (const float*)d_in[15];
    const float* msgW2 = (const float*)d_in[16];
    const float* msgb2 = (const float*)d_in[17];
    const float* updW1 = (const float*)d_in[18];
    const float* updb1 = (const float*)d_in[19];
    const float* updW2 = (const float*)d_in[20];
    const float* updb2 = (const float*)d_in[21];
    const float* Wo1   = (const float*)d_in[22];
    const float* bo1   = (const float*)d_in[23];
    const float* Wo2   = (const float*)d_in[24];
    const float* bo2   = (const float*)d_in[25];

    float *t1, *h, *br, *eH, *eM, *agg, *pooled, *cnt;
    cudaGetSymbolAddress((void**)&t1,     g_t1);
    cudaGetSymbolAddress((void**)&h,      g_h);
    cudaGetSymbolAddress((void**)&br,     g_br);
    cudaGetSymbolAddress((void**)&eH,     g_eH);
    cudaGetSymbolAddress((void**)&eM,     g_eM);
    cudaGetSymbolAddress((void**)&agg,    g_agg);
    cudaGetSymbolAddress((void**)&pooled, g_pooled);
    cudaGetSymbolAddress((void**)&cnt,    g_cnt);

    const int* src = ei;
    const int* dst = ei + E_;

    // ---- input MLP: h = silu(x@Wi1+b)@Wi2+b ----
    gemm_3xtf32<<<gemm_grid(N_, HID_), 256>>>(x,  nullptr, x,  IN_,  Wi1, bi1, nullptr, t1, N_, HID_, IN_,  1);
    gemm_3xtf32<<<gemm_grid(N_, D_),   256>>>(t1, nullptr, t1, HID_, Wi2, bi2, nullptr, h,  N_, D_,   HID_, 0);

    // ---- message passing layers ----
    for (int l = 0; l < NL_; l++) {
        const float* mW1 = msgW1 + (size_t)l * D2_ * HID_;
        const float* mb1 = msgb1 + (size_t)l * HID_;
        const float* mW2 = msgW2 + (size_t)l * HID_ * D_;
        const float* mb2 = msgb2 + (size_t)l * D_;
        const float* uW1 = updW1 + (size_t)l * D2_ * HID_;
        const float* ub1 = updb1 + (size_t)l * HID_;
        const float* uW2 = updW2 + (size_t)l * HID_ * D_;
        const float* ub2 = updb2 + (size_t)l * D_;

        edge_bracket_kernel<<<E_, 128>>>(h, ei, sci, scj, sck, scc, br);

        // message MLP: A operand = [h[src] | br]  (no eA materialization)
        gemm_3xtf32<<<gemm_grid(E_, HID_), 256>>>(h,  src,     br, D_,   mW1, mb1, nullptr, eH, E_, HID_, D2_,  1);
        gemm_3xtf32<<<gemm_grid(E_, D_),   256>>>(eH, nullptr, eH, HID_, mW2, mb2, nullptr, eM, E_, D_,   HID_, 0);

        {
            size_t n = (size_t)N_ * D_;
            zero_kernel<<<(unsigned)((n + 255) / 256), 256>>>(agg, n);
        }
        scatter_add_kernel<<<E_, 256>>>(eM, dst, agg);

        // update MLP: A operand = [h | agg]  (no concat materialization)
        gemm_3xtf32<<<gemm_grid(N_, HID_), 256>>>(h,  nullptr, agg, D_,  uW1, ub1, nullptr, t1, N_, HID_, D2_,  1);
        gemm_3xtf32<<<gemm_grid(N_, D_),   256>>>(t1, nullptr, t1, HID_, uW2, ub2, h,       h,  N_, D_,   HID_, 0);
    }

    // ---- killing form + pooling ----
    {
        size_t n = NG_ * DP1_;
        zero_kernel<<<(unsigned)((n + 255) / 256), 256>>>(pooled, n);
        zero_kernel<<<1, NG_>>>(cnt, NG_);
    }
    killing_pool_kernel<<<N_, 128>>>(h, batch, kbr, kbc, kbv, pooled, cnt);

    // ---- final MLP ----
    final_mlp_kernel<<<NG_, 256>>>(pooled, cnt, Wo1, bo1, Wo2, bo2, (float*)d_out);
}

// round 5
// speedup vs baseline: 2.3438x; 1.0441x over previous
#include <cuda_runtime.h>
#include <cuda_bf16.h>
#include <math.h>
#include <stdint.h>

// ---------------- problem constants ----------------
constexpr int N_   = 20000;   // nodes
constexpr int E_   = 100000;  // edges
constexpr int D_   = 248;     // Lie algebra dim
constexpr int HID_ = 256;     // MLP hidden
constexpr int IN_  = 128;     // input feature dim
constexpr int OUT_ = 16;      // output dim
constexpr int NL_  = 4;       // layers
constexpr int NNZ_ = 512;     // structure constant nnz
constexpr int NB_  = 1024;    // killing form nnz
constexpr int NG_  = 128;     // graphs
constexpr int D2_  = 2 * D_;  // 496
constexpr int DP1_ = D_ + 1;  // 249

// ---------------- scratch (device globals; allocation is forbidden) ----------------
__device__ float g_t1[(size_t)N_ * HID_];    // node hidden
__device__ float g_h[(size_t)N_ * D_];       // node features h
__device__ float g_br[(size_t)E_ * D_];      // per-edge Lie bracket
__device__ float g_eH[(size_t)E_ * HID_];    // edge hidden
__device__ float g_agg[(size_t)N_ * D_];     // aggregated messages
__device__ float g_pooled[NG_ * DP1_];
__device__ float g_cnt[NG_];

__device__ __forceinline__ float silu_f(float v) {
    return v / (1.0f + expf(-v));
}

__device__ __forceinline__ float to_tf32(float x) {
    uint32_t u;
    asm("cvt.rna.tf32.f32 %0, %1;" : "=r"(u) : "f"(x));
    return __uint_as_float(u);
}

// ---------------- 3xTF32 tensor-core GEMM, double-buffered, split-K A ----------------
// C = act(A @ W + bias) (+ res)   OR  (scatter mode, dstIdx != null):
//     atomicAdd(Cagg[dstIdx[m] * N + n], (A@W + bias)[m,n])
// A operand columns [0, K1)  from A1 (row gathered via gidx if non-null, stride K1)
// A operand columns [K1, K)  from A2 (direct row, stride K-K1)
// W: K x N row-major. Requires K % 8 == 0, K1 % 4 == 0, N % 4 == 0.
constexpr int BM = 128, BN = 128, BK = 8;
constexpr int APAD = 12;      // A row stride (conflict-free frag reads)
constexpr int WPAD = 136;     // W row stride (conflict-free frag reads)

__global__ __launch_bounds__(256, 2) void gemm_3xtf32(
    const float* __restrict__ A1, const int* __restrict__ gidx,
    const float* __restrict__ A2, int K1,
    const float* __restrict__ W, const float* __restrict__ bias,
    const float* __restrict__ res, const int* __restrict__ dstIdx,
    float* __restrict__ C, int M, int N, int K, int act)
{
    __shared__ float AsH[2][BM][APAD];
    __shared__ float AsL[2][BM][APAD];
    __shared__ float WsH[2][BK][WPAD];
    __shared__ float WsL[2][BK][WPAD];

    const int tid  = threadIdx.x;
    const int lane = tid & 31;
    const int wid  = tid >> 5;
    const int row0 = blockIdx.y * BM;
    const int col0 = blockIdx.x * BN;

    // ---- global load mappings (1 float4 per thread per operand per stage) ----
    const int aRow = tid >> 1;              // 0..127
    const int aKq  = (tid & 1) * 4;         // 0 or 4
    const int wK   = tid >> 5;              // 0..7
    const int wCol = (tid & 31) * 4;        // 0..124

    const int K2s = K - K1;                 // stride of A2

    const int gRowA = row0 + aRow;
    const bool av = gRowA < M;
    size_t a1off = 0, a2off = 0;
    if (av) {
        int r = gidx ? __ldg(&gidx[gRowA]) : gRowA;
        a1off = (size_t)r * K1;
        a2off = (size_t)gRowA * K2s;
    }
    const int gnW = col0 + wCol;
    const bool wv = gnW < N;                // N%4==0 covers the float4

    // warp tile: 32 (m) x 64 (n); warps 4x2
    const int wm = (wid & 3) * 32;
    const int wn = (wid >> 2) * 64;
    const int grp = lane >> 2;
    const int qid = lane & 3;

    float acc[2][8][4];
    #pragma unroll
    for (int mt = 0; mt < 2; mt++)
        #pragma unroll
        for (int nt = 0; nt < 8; nt++)
            #pragma unroll
            for (int c = 0; c < 4; c++) acc[mt][nt][c] = 0.0f;

    auto loadA = [&](int k0) -> float4 {
        if (!av) return make_float4(0.f, 0.f, 0.f, 0.f);
        int kg = k0 + aKq;
        if (kg < K1) return *(const float4*)&A1[a1off + kg];
        return *(const float4*)&A2[a2off + (kg - K1)];
    };
    auto loadW = [&](int k0) -> float4 {
        if (!wv) return make_float4(0.f, 0.f, 0.f, 0.f);
        return *(const float4*)&W[(size_t)(k0 + wK) * N + gnW];
    };
    auto stage = [&](int buf, float4 av4, float4 wv4) {
        float h0 = to_tf32(av4.x), h1 = to_tf32(av4.y), h2 = to_tf32(av4.z), h3 = to_tf32(av4.w);
        *(float4*)&AsH[buf][aRow][aKq] = make_float4(h0, h1, h2, h3);
        *(float4*)&AsL[buf][aRow][aKq] =
            make_float4(to_tf32(av4.x - h0), to_tf32(av4.y - h1),
                        to_tf32(av4.z - h2), to_tf32(av4.w - h3));
        h0 = to_tf32(wv4.x); h1 = to_tf32(wv4.y); h2 = to_tf32(wv4.z); h3 = to_tf32(wv4.w);
        *(float4*)&WsH[buf][wK][wCol] = make_float4(h0, h1, h2, h3);
        *(float4*)&WsL[buf][wK][wCol] =
            make_float4(to_tf32(wv4.x - h0), to_tf32(wv4.y - h1),
                        to_tf32(wv4.z - h2), to_tf32(wv4.w - h3));
    };

    // prologue: stage tile 0, prefetch tile 1
    float4 aR = loadA(0), wR = loadW(0);
    stage(0, aR, wR);
    if (BK < K) { aR = loadA(BK); wR = loadW(BK); }
    __syncthreads();

    for (int k0 = 0; k0 < K; k0 += BK) {
        const int buf = (k0 >> 3) & 1;
        // stage next tile into the other buffer (overlaps with MMA below)
        if (k0 + BK < K) stage(buf ^ 1, aR, wR);
        if (k0 + 2 * BK < K) { aR = loadA(k0 + 2 * BK); wR = loadW(k0 + 2 * BK); }

        uint32_t ah[2][4], al[2][4];
        #pragma unroll
        for (int mt = 0; mt < 2; mt++) {
            const int ar = wm + 16 * mt + grp;
            ah[mt][0] = __float_as_uint(AsH[buf][ar    ][qid]);
            ah[mt][1] = __float_as_uint(AsH[buf][ar + 8][qid]);
            ah[mt][2] = __float_as_uint(AsH[buf][ar    ][qid + 4]);
            ah[mt][3] = __float_as_uint(AsH[buf][ar + 8][qid + 4]);
            al[mt][0] = __float_as_uint(AsL[buf][ar    ][qid]);
            al[mt][1] = __float_as_uint(AsL[buf][ar + 8][qid]);
            al[mt][2] = __float_as_uint(AsL[buf][ar    ][qid + 4]);
            al[mt][3] = __float_as_uint(AsL[buf][ar + 8][qid + 4]);
        }
        #pragma unroll
        for (int nt = 0; nt < 8; nt++) {
            const int bc = wn + 8 * nt + grp;
            uint32_t bh0 = __float_as_uint(WsH[buf][qid    ][bc]);
            uint32_t bh1 = __float_as_uint(WsH[buf][qid + 4][bc]);
            uint32_t bl0 = __float_as_uint(WsL[buf][qid    ][bc]);
            uint32_t bl1 = __float_as_uint(WsL[buf][qid + 4][bc]);
            #pragma unroll
            for (int mt = 0; mt < 2; mt++) {
                #define MMA_TF32(Afr, B0, B1)                                          \
                    asm volatile(                                                      \
                        "mma.sync.aligned.m16n8k8.row.col.f32.tf32.tf32.f32 "          \
                        "{%0,%1,%2,%3}, {%4,%5,%6,%7}, {%8,%9}, {%0,%1,%2,%3};"        \
                        : "+f"(acc[mt][nt][0]), "+f"(acc[mt][nt][1]),                  \
                          "+f"(acc[mt][nt][2]), "+f"(acc[mt][nt][3])                   \
                        : "r"(Afr[mt][0]), "r"(Afr[mt][1]),                            \
                          "r"(Afr[mt][2]), "r"(Afr[mt][3]),                            \
                          "r"(B0), "r"(B1))
                MMA_TF32(ah, bh0, bh1);   // hi * hi
                MMA_TF32(al, bh0, bh1);   // lo * hi
                MMA_TF32(ah, bl0, bl1);   // hi * lo
                #undef MMA_TF32
            }
        }
        __syncthreads();
    }

    // ---- epilogue ----
    #pragma unroll
    for (int mt = 0; mt < 2; mt++) {
        #pragma unroll
        for (int rr = 0; rr < 2; rr++) {
            const int gm = row0 + wm + 16 * mt + grp + rr * 8;
            if (gm >= M) continue;
            int drow = 0;
            if (dstIdx) drow = __ldg(&dstIdx[gm]);
            #pragma unroll
            for (int nt = 0; nt < 8; nt++) {
                const int gn = col0 + wn + 8 * nt + qid * 2;
                if (gn >= N) continue;   // N even, pair aligned
                float2 bb = __ldg((const float2*)&bias[gn]);
                float v0 = acc[mt][nt][rr * 2 + 0] + bb.x;
                float v1 = acc[mt][nt][rr * 2 + 1] + bb.y;
                if (act) { v0 = silu_f(v0); v1 = silu_f(v1); }
                if (dstIdx) {
                    atomicAdd(&C[(size_t)drow * N + gn],     v0);
                    atomicAdd(&C[(size_t)drow * N + gn + 1], v1);
                } else {
                    if (res) {
                        float2 rv = *(const float2*)&res[(size_t)gm * N + gn];
                        v0 += rv.x; v1 += rv.y;
                    }
                    *(float2*)&C[(size_t)gm * N + gn] = make_float2(v0, v1);
                }
            }
        }
    }
}

// ---------------- edge gather + Lie bracket -> br (8 edges/block, warp/edge) ----
constexpr int EPB = 8;
__global__ __launch_bounds__(256) void edge_bracket_kernel(
    const float* __restrict__ h, const int* __restrict__ ei,
    const int* __restrict__ sci, const int* __restrict__ scj,
    const int* __restrict__ sck, const float* __restrict__ scc,
    float* __restrict__ br)
{
    __shared__ int   s_i[NNZ_], s_j[NNZ_], s_k[NNZ_];
    __shared__ float s_c[NNZ_];
    __shared__ float hs[EPB][D_], hd[EPB][D_], brs[EPB][D_];

    const int tid = threadIdx.x;
    for (int t = tid; t < NNZ_; t += 256) {
        s_i[t] = __ldg(&sci[t]);
        s_j[t] = __ldg(&scj[t]);
        s_k[t] = __ldg(&sck[t]);
        s_c[t] = __ldg(&scc[t]);
    }
    __syncthreads();

    const int w = tid >> 5, lane = tid & 31;
    const int e = blockIdx.x * EPB + w;
    if (e >= E_) return;
    const int s = __ldg(&ei[e]);
    const int d = __ldg(&ei[E_ + e]);

    const float4* hsrc = (const float4*)(h + (size_t)s * D_);
    const float4* hdst = (const float4*)(h + (size_t)d * D_);
    #pragma unroll
    for (int q = lane; q < D_ / 4; q += 32) {
        ((float4*)hs[w])[q] = hsrc[q];
        ((float4*)hd[w])[q] = hdst[q];
    }
    for (int k = lane; k < D_; k += 32) brs[w][k] = 0.0f;
    __syncwarp();

    #pragma unroll
    for (int t = lane; t < NNZ_; t += 32) {
        float v = s_c[t] * hs[w][s_i[t]] * hd[w][s_j[t]];
        atomicAdd(&brs[w][s_k[t]], v);
    }
    __syncwarp();

    float4* row = (float4*)(br + (size_t)e * D_);
    #pragma unroll
    for (int q = lane; q < D_ / 4; q += 32)
        row[q] = ((const float4*)brs[w])[q];
}

__global__ void zero_kernel(float* __restrict__ p, size_t n) {
    size_t idx = (size_t)blockIdx.x * blockDim.x + threadIdx.x;
    if (idx < n) p[idx] = 0.0f;
}

// ---------------- killing form + pooling (scatter to graphs) ----------------
__global__ __launch_bounds__(128) void killing_pool_kernel(
    const float* __restrict__ h, const int* __restrict__ batch,
    const int* __restrict__ kbr, const int* __restrict__ kbc,
    const float* __restrict__ kbv,
    float* __restrict__ pooled, float* __restrict__ cnt)
{
    const int n = blockIdx.x;
    __shared__ float hrow[D_];
    __shared__ float wsum[4];
    for (int k = threadIdx.x; k < D_; k += 128)
        hrow[k] = h[(size_t)n * D_ + k];
    __syncthreads();

    float s = 0.0f;
    for (int t = threadIdx.x; t < NB_; t += 128)
        s += __ldg(&kbv[t]) * hrow[__ldg(&kbr[t])] * hrow[__ldg(&kbc[t])];
    #pragma unroll
    for (int off = 16; off > 0; off >>= 1)
        s += __shfl_down_sync(0xffffffffu, s, off);
    if ((threadIdx.x & 31) == 0) wsum[threadIdx.x >> 5] = s;
    __syncthreads();

    const int b = __ldg(&batch[n]);
    for (int k = threadIdx.x; k < D_; k += 128)
        atomicAdd(&pooled[b * DP1_ + k], hrow[k]);
    if (threadIdx.x == 0) {
        float ks = wsum[0] + wsum[1] + wsum[2] + wsum[3];
        atomicAdd(&pooled[b * DP1_ + D_], ks);
        atomicAdd(&cnt[b], 1.0f);
    }
}

// ---------------- final MLP per graph ----------------
__global__ __launch_bounds__(256) void final_mlp_kernel(
    const float* __restrict__ pooled, const float* __restrict__ cnt,
    const float* __restrict__ Wo1, const float* __restrict__ bo1,
    const float* __restrict__ Wo2, const float* __restrict__ bo2,
    float* __restrict__ out)
{
    const int g = blockIdx.x;
    __shared__ float p[DP1_];
    __shared__ float hid[HID_];
    const float c = fmaxf(cnt[g], 1.0f);
    for (int k = threadIdx.x; k < DP1_; k += 256)
        p[k] = pooled[g * DP1_ + k] / c;
    __syncthreads();

    const int j = threadIdx.x;
    float s = __ldg(&bo1[j]);
    for (int k = 0; k < DP1_; k++)
        s = fmaf(p[k], __ldg(&Wo1[k * HID_ + j]), s);
    hid[j] = silu_f(s);
    __syncthreads();

    if (j < OUT_) {
        float o = __ldg(&bo2[j]);
        for (int k = 0; k < HID_; k++)
            o = fmaf(hid[k], __ldg(&Wo2[k * OUT_ + j]), o);
        out[g * OUT_ + j] = o;
    }
}

// ---------------- host driver ----------------
static inline dim3 gemm_grid(int M, int N) {
    return dim3((N + BN - 1) / BN, (M + BM - 1) / BM);
}

extern "C" void kernel_launch(void* const* d_in, const int* in_sizes, int n_in,
                              void* d_out, int out_size)
{
    const float* x     = (const float*)d_in[0];
    const int*   ei    = (const int*)  d_in[1];
    const int*   batch = (const int*)  d_in[2];
    const int*   sci   = (const int*)  d_in[3];
    const int*   scj   = (const int*)  d_in[4];
    const int*   sck   = (const int*)  d_in[5];
    const float* scc   = (const float*)d_in[6];
    const int*   kbr   = (const int*)  d_in[7];
    const int*   kbc   = (const int*)  d_in[8];
    const float* kbv   = (const float*)d_in[9];
    const float* Wi1   = (const float*)d_in[10];
    const float* bi1   = (const float*)d_in[11];
    const float* Wi2   = (const float*)d_in[12];
    const float* bi2   = (const float*)d_in[13];
    const float* msgW1 = (const float*)d_in[14];
    const float* msgb1 = (const float*)d_in[15];
    const float* msgW2 = (const float*)d_in[16];
    const float* msgb2 = (const float*)d_in[17];
    const float* updW1 = (const float*)d_in[18];
    const float* updb1 = (const float*)d_in[19];
    const float* updW2 = (const float*)d_in[20];
    const float* updb2 = (const float*)d_in[21];
    const float* Wo1   = (const float*)d_in[22];
    const float* bo1   = (const float*)d_in[23];
    const float* Wo2   = (const float*)d_in[24];
    const float* bo2   = (const float*)d_in[25];

    float *t1, *h, *br, *eH, *agg, *pooled, *cnt;
    cudaGetSymbolAddress((void**)&t1,     g_t1);
    cudaGetSymbolAddress((void**)&h,      g_h);
    cudaGetSymbolAddress((void**)&br,     g_br);
    cudaGetSymbolAddress((void**)&eH,     g_eH);
    cudaGetSymbolAddress((void**)&agg,    g_agg);
    cudaGetSymbolAddress((void**)&pooled, g_pooled);
    cudaGetSymbolAddress((void**)&cnt,    g_cnt);

    const int* src = ei;
    const int* dst = ei + E_;

    // ---- input MLP: h = silu(x@Wi1+b)@Wi2+b ----
    gemm_3xtf32<<<gemm_grid(N_, HID_), 256>>>(x,  nullptr, x,  IN_,  Wi1, bi1, nullptr, nullptr, t1, N_, HID_, IN_,  1);
    gemm_3xtf32<<<gemm_grid(N_, D_),   256>>>(t1, nullptr, t1, HID_, Wi2, bi2, nullptr, nullptr, h,  N_, D_,   HID_, 0);

    // ---- message passing layers ----
    for (int l = 0; l < NL_; l++) {
        const float* mW1 = msgW1 + (size_t)l * D2_ * HID_;
        const float* mb1 = msgb1 + (size_t)l * HID_;
        const float* mW2 = msgW2 + (size_t)l * HID_ * D_;
        const float* mb2 = msgb2 + (size_t)l * D_;
        const float* uW1 = updW1 + (size_t)l * D2_ * HID_;
        const float* ub1 = updb1 + (size_t)l * HID_;
        const float* uW2 = updW2 + (size_t)l * HID_ * D_;
        const float* ub2 = updb2 + (size_t)l * D_;

        edge_bracket_kernel<<<(E_ + EPB - 1) / EPB, 256>>>(h, ei, sci, scj, sck, scc, br);

        // message MLP layer 1: A = [h[src] | br]
        gemm_3xtf32<<<gemm_grid(E_, HID_), 256>>>(h,  src, br, D_, mW1, mb1, nullptr, nullptr, eH, E_, HID_, D2_, 1);

        // zero agg, then message MLP layer 2 with fused scatter-add into agg
        {
            size_t n = (size_t)N_ * D_;
            zero_kernel<<<(unsigned)((n + 255) / 256), 256>>>(agg, n);
        }
        gemm_3xtf32<<<gemm_grid(E_, D_), 256>>>(eH, nullptr, eH, HID_, mW2, mb2, nullptr, dst, agg, E_, D_, HID_, 0);

        // update MLP: A = [h | agg]
        gemm_3xtf32<<<gemm_grid(N_, HID_), 256>>>(h,  nullptr, agg, D_,  uW1, ub1, nullptr, nullptr, t1, N_, HID_, D2_, 1);
        gemm_3xtf32<<<gemm_grid(N_, D_),   256>>>(t1, nullptr, t1,  HID_, uW2, ub2, h,      nullptr, h,  N_, D_,   HID_, 0);
    }

    // ---- killing form + pooling ----
    {
        size_t n = NG_ * DP1_;
        zero_kernel<<<(unsigned)((n + 255) / 256), 256>>>(pooled, n);
        zero_kernel<<<1, NG_>>>(cnt, NG_);
    }
    killing_pool_kernel<<<N_, 128>>>(h, batch, kbr, kbc, kbv, pooled, cnt);

    // ---- final MLP ----
    final_mlp_kernel<<<NG_, 256>>>(pooled, cnt, Wo1, bo1, Wo2, bo2, (float*)d_out);
}

// round 7
// speedup vs baseline: 3.2272x; 1.3769x over previous
#include <cuda_runtime.h>
#include <cuda_bf16.h>
#include <math.h>
#include <stdint.h>

// ---------------- problem constants ----------------
constexpr int N_   = 20000;   // nodes
constexpr int E_   = 100000;  // edges
constexpr int D_   = 248;     // Lie algebra dim
constexpr int HID_ = 256;     // MLP hidden
constexpr int IN_  = 128;     // input feature dim
constexpr int OUT_ = 16;      // output dim
constexpr int NL_  = 4;       // layers
constexpr int NNZ_ = 512;     // structure constant nnz
constexpr int NB_  = 1024;    // killing form nnz
constexpr int NG_  = 128;     // graphs
constexpr int D2_  = 2 * D_;  // 496
constexpr int DP1_ = D_ + 1;  // 249

// ---------------- scratch (device globals; allocation is forbidden) ----------------
__device__ float g_t1[(size_t)N_ * HID_];    // node hidden
__device__ float g_h[(size_t)N_ * D_];       // node features h
__device__ float g_br[(size_t)E_ * D_];      // per-edge Lie bracket
__device__ float g_eH[(size_t)E_ * HID_];    // edge hidden
__device__ float g_agg[(size_t)N_ * D_];     // aggregated messages
__device__ float g_pooled[NG_ * DP1_];
__device__ float g_cnt[NG_];

__device__ __forceinline__ float silu_f(float v) {
    return v / (1.0f + expf(-v));
}

__device__ __forceinline__ uint32_t pack_bf16(float a, float b) {
    __nv_bfloat162 t = __floats2bfloat162_rn(a, b);   // a -> low, b -> high
    return *(uint32_t*)&t;
}
__device__ __forceinline__ float bf16_round(float x) {
    return __bfloat162float(__float2bfloat16(x));
}

// ---------------- 3xBF16 tensor-core GEMM, double-buffered, split-K A ----------------
// C = act(A @ W + bias) (+ res)   OR  (scatter mode, dstIdx != null):
//     atomicAdd(Cagg[dstIdx[m] * N + n], (A@W + bias)[m,n])
// fp32-grade accuracy via hi/lo bf16 decomposition:
//   x = hi + lo (hi = bf16(x), lo = bf16(x - hi));  A@W ~= Ah@Wh + Al@Wh + Ah@Wl
// A operand columns [0, K1)  from A1 (row gathered via gidx if non-null, stride K1)
// A operand columns [K1, K)  from A2 (direct row, stride K-K1)
// W: K x N row-major. Requires K % 16 == 0, K1 % 8 == 0, N % 4 == 0.
constexpr int BM = 128, BN = 128, BK = 16;
constexpr int PA = 12;   // uint32 words per A smem row (8 pairs + pad, 48B: 16B-aligned)
constexpr int PW = 136;  // uint32 words per W smem p-row (544B: 16B-aligned)

__global__ __launch_bounds__(256, 2) void gemm_3xbf16(
    const float* __restrict__ A1, const int* __restrict__ gidx,
    const float* __restrict__ A2, int K1,
    const float* __restrict__ W, const float* __restrict__ bias,
    const float* __restrict__ res, const int* __restrict__ dstIdx,
    float* __restrict__ C, int M, int N, int K, int act)
{
    __shared__ uint32_t AsH[2][BM][PA];
    __shared__ uint32_t AsL[2][BM][PA];
    __shared__ uint32_t WsH[2][8][PW];
    __shared__ uint32_t WsL[2][8][PW];

    const int tid  = threadIdx.x;
    const int lane = tid & 31;
    const int wid  = tid >> 5;
    const int row0 = blockIdx.y * BM;
    const int col0 = blockIdx.x * BN;

    // ---- staging mappings ----
    const int aRow = tid >> 1;            // 0..127
    const int aK8  = (tid & 1) * 8;       // 0 or 8 (k offset within tile)
    const int wKr  = (tid >> 5) * 2;      // 0,2,..,14 (k row pair base)
    const int wCol = lane * 4;            // 0..124

    const int K2s = K - K1;               // stride of A2

    const int gRowA = row0 + aRow;
    const bool av = gRowA < M;
    size_t a1off = 0, a2off = 0;
    if (av) {
        int r = gidx ? __ldg(&gidx[gRowA]) : gRowA;
        a1off = (size_t)r * K1;
        a2off = (size_t)gRowA * K2s;
    }
    const int gnW = col0 + wCol;
    const bool wv = gnW < N;              // N%4==0 covers the float4

    // warp tile: 32 (m) x 64 (n); warps 4x2
    const int wm = (wid & 3) * 32;
    const int wn = (wid >> 2) * 64;
    const int grp = lane >> 2;
    const int qid = lane & 3;

    float acc[2][8][4];
    #pragma unroll
    for (int mt = 0; mt < 2; mt++)
        #pragma unroll
        for (int nt = 0; nt < 8; nt++)
            #pragma unroll
            for (int c = 0; c < 4; c++) acc[mt][nt][c] = 0.0f;

    // kg guaranteed multiple of 4 and never straddles K1 (K1 % 8 == 0)
    auto loadA4 = [&](int kg) -> float4 {
        if (!av) return make_float4(0.f, 0.f, 0.f, 0.f);
        if (kg < K1) return *(const float4*)&A1[a1off + kg];
        return *(const float4*)&A2[a2off + (kg - K1)];
    };
    auto loadW4 = [&](int krow) -> float4 {
        if (!wv) return make_float4(0.f, 0.f, 0.f, 0.f);
        return *(const float4*)&W[(size_t)krow * N + gnW];
    };

    float4 aV0, aV1, wV0, wV1;
    auto prefetch = [&](int k0) {
        aV0 = loadA4(k0 + aK8);
        aV1 = loadA4(k0 + aK8 + 4);
        wV0 = loadW4(k0 + wKr);
        wV1 = loadW4(k0 + wKr + 1);
    };
    auto stage = [&](int buf) {
        // A: pairs along k within one row
        float h0 = bf16_round(aV0.x), h1 = bf16_round(aV0.y),
              h2 = bf16_round(aV0.z), h3 = bf16_round(aV0.w),
              h4 = bf16_round(aV1.x), h5 = bf16_round(aV1.y),
              h6 = bf16_round(aV1.z), h7 = bf16_round(aV1.w);
        uint4 hi = make_uint4(pack_bf16(h0, h1), pack_bf16(h2, h3),
                              pack_bf16(h4, h5), pack_bf16(h6, h7));
        uint4 lo = make_uint4(pack_bf16(aV0.x - h0, aV0.y - h1),
                              pack_bf16(aV0.z - h2, aV0.w - h3),
                              pack_bf16(aV1.x - h4, aV1.y - h5),
                              pack_bf16(aV1.z - h6, aV1.w - h7));
        *(uint4*)&AsH[buf][aRow][aK8 / 2] = hi;
        *(uint4*)&AsL[buf][aRow][aK8 / 2] = lo;
        // W: pairs along k across two k-rows, per column
        float g0 = bf16_round(wV0.x), g1 = bf16_round(wV0.y),
              g2 = bf16_round(wV0.z), g3 = bf16_round(wV0.w),
              g4 = bf16_round(wV1.x), g5 = bf16_round(wV1.y),
              g6 = bf16_round(wV1.z), g7 = bf16_round(wV1.w);
        uint4 whi = make_uint4(pack_bf16(g0, g4), pack_bf16(g1, g5),
                               pack_bf16(g2, g6), pack_bf16(g3, g7));
        uint4 wlo = make_uint4(pack_bf16(wV0.x - g0, wV1.x - g4),
                               pack_bf16(wV0.y - g1, wV1.y - g5),
                               pack_bf16(wV0.z - g2, wV1.z - g6),
                               pack_bf16(wV0.w - g3, wV1.w - g7));
        *(uint4*)&WsH[buf][wKr / 2][wCol] = whi;
        *(uint4*)&WsL[buf][wKr / 2][wCol] = wlo;
    };

    // prologue: stage tile 0, prefetch tile 1
    prefetch(0);
    stage(0);
    if (BK < K) prefetch(BK);
    __syncthreads();

    for (int k0 = 0; k0 < K; k0 += BK) {
        const int buf = (k0 >> 4) & 1;
        if (k0 + BK < K) stage(buf ^ 1);
        if (k0 + 2 * BK < K) prefetch(k0 + 2 * BK);

        uint32_t ah[2][4], al[2][4];
        #pragma unroll
        for (int mt = 0; mt < 2; mt++) {
            const int ar = wm + 16 * mt + grp;
            ah[mt][0] = AsH[buf][ar    ][qid];
            ah[mt][1] = AsH[buf][ar + 8][qid];
            ah[mt][2] = AsH[buf][ar    ][qid + 4];
            ah[mt][3] = AsH[buf][ar + 8][qid + 4];
            al[mt][0] = AsL[buf][ar    ][qid];
            al[mt][1] = AsL[buf][ar + 8][qid];
            al[mt][2] = AsL[buf][ar    ][qid + 4];
            al[mt][3] = AsL[buf][ar + 8][qid + 4];
        }
        #pragma unroll
        for (int nt = 0; nt < 8; nt++) {
            const int bc = wn + 8 * nt + grp;
            uint32_t bh0 = WsH[buf][qid    ][bc];
            uint32_t bh1 = WsH[buf][qid + 4][bc];
            uint32_t bl0 = WsL[buf][qid    ][bc];
            uint32_t bl1 = WsL[buf][qid + 4][bc];
            #pragma unroll
            for (int mt = 0; mt < 2; mt++) {
                #define MMA_BF16(Afr, B0, B1)                                          \
                    asm volatile(                                                      \
                        "mma.sync.aligned.m16n8k16.row.col.f32.bf16.bf16.f32 "         \
                        "{%0,%1,%2,%3}, {%4,%5,%6,%7}, {%8,%9}, {%0,%1,%2,%3};"        \
                        : "+f"(acc[mt][nt][0]), "+f"(acc[mt][nt][1]),                  \
                          "+f"(acc[mt][nt][2]), "+f"(acc[mt][nt][3])                   \
                        : "r"(Afr[mt][0]), "r"(Afr[mt][1]),                            \
                          "r"(Afr[mt][2]), "r"(Afr[mt][3]),                            \
                          "r"(B0), "r"(B1))
                MMA_BF16(ah, bh0, bh1);   // hi * hi
                MMA_BF16(al, bh0, bh1);   // lo * hi
                MMA_BF16(ah, bl0, bl1);   // hi * lo
                #undef MMA_BF16
            }
        }
        __syncthreads();
    }

    // ---- epilogue ----
    #pragma unroll
    for (int mt = 0; mt < 2; mt++) {
        #pragma unroll
        for (int rr = 0; rr < 2; rr++) {
            const int gm = row0 + wm + 16 * mt + grp + rr * 8;
            if (gm >= M) continue;
            int drow = 0;
            if (dstIdx) drow = __ldg(&dstIdx[gm]);
            #pragma unroll
            for (int nt = 0; nt < 8; nt++) {
                const int gn = col0 + wn + 8 * nt + qid * 2;
                if (gn >= N) continue;   // N even, pair aligned
                float2 bb = __ldg((const float2*)&bias[gn]);
                float v0 = acc[mt][nt][rr * 2 + 0] + bb.x;
                float v1 = acc[mt][nt][rr * 2 + 1] + bb.y;
                if (act) { v0 = silu_f(v0); v1 = silu_f(v1); }
                if (dstIdx) {
                    atomicAdd(&C[(size_t)drow * N + gn],     v0);
                    atomicAdd(&C[(size_t)drow * N + gn + 1], v1);
                } else {
                    if (res) {
                        float2 rv = *(const float2*)&res[(size_t)gm * N + gn];
                        v0 += rv.x; v1 += rv.y;
                    }
                    *(float2*)&C[(size_t)gm * N + gn] = make_float2(v0, v1);
                }
            }
        }
    }
}

// ---------------- edge gather + Lie bracket -> br (8 edges/block, warp/edge) ----
constexpr int EPB = 8;
__global__ __launch_bounds__(256) void edge_bracket_kernel(
    const float* __restrict__ h, const int* __restrict__ ei,
    const int* __restrict__ sci, const int* __restrict__ scj,
    const int* __restrict__ sck, const float* __restrict__ scc,
    float* __restrict__ br)
{
    __shared__ int   s_i[NNZ_], s_j[NNZ_], s_k[NNZ_];
    __shared__ float s_c[NNZ_];
    __shared__ float hs[EPB][D_], hd[EPB][D_], brs[EPB][D_];

    const int tid = threadIdx.x;
    for (int t = tid; t < NNZ_; t += 256) {
        s_i[t] = __ldg(&sci[t]);
        s_j[t] = __ldg(&scj[t]);
        s_k[t] = __ldg(&sck[t]);
        s_c[t] = __ldg(&scc[t]);
    }
    __syncthreads();

    const int w = tid >> 5, lane = tid & 31;
    const int e = blockIdx.x * EPB + w;
    if (e >= E_) return;
    const int s = __ldg(&ei[e]);
    const int d = __ldg(&ei[E_ + e]);

    const float4* hsrc = (const float4*)(h + (size_t)s * D_);
    const float4* hdst = (const float4*)(h + (size_t)d * D_);
    #pragma unroll
    for (int q = lane; q < D_ / 4; q += 32) {
        ((float4*)hs[w])[q] = hsrc[q];
        ((float4*)hd[w])[q] = hdst[q];
    }
    for (int k = lane; k < D_; k += 32) brs[w][k] = 0.0f;
    __syncwarp();

    #pragma unroll
    for (int t = lane; t < NNZ_; t += 32) {
        float v = s_c[t] * hs[w][s_i[t]] * hd[w][s_j[t]];
        atomicAdd(&brs[w][s_k[t]], v);
    }
    __syncwarp();

    float4* row = (float4*)(br + (size_t)e * D_);
    #pragma unroll
    for (int q = lane; q < D_ / 4; q += 32)
        row[q] = ((const float4*)brs[w])[q];
}

__global__ void zero_kernel(float* __restrict__ p, size_t n) {
    size_t idx = (size_t)blockIdx.x * blockDim.x + threadIdx.x;
    if (idx < n) p[idx] = 0.0f;
}

// ---------------- killing form + pooling (scatter to graphs) ----------------
__global__ __launch_bounds__(128) void killing_pool_kernel(
    const float* __restrict__ h, const int* __restrict__ batch,
    const int* __restrict__ kbr, const int* __restrict__ kbc,
    const float* __restrict__ kbv,
    float* __restrict__ pooled, float* __restrict__ cnt)
{
    const int n = blockIdx.x;
    __shared__ float hrow[D_];
    __shared__ float wsum[4];
    for (int k = threadIdx.x; k < D_; k += 128)
        hrow[k] = h[(size_t)n * D_ + k];
    __syncthreads();

    float s = 0.0f;
    for (int t = threadIdx.x; t < NB_; t += 128)
        s += __ldg(&kbv[t]) * hrow[__ldg(&kbr[t])] * hrow[__ldg(&kbc[t])];
    #pragma unroll
    for (int off = 16; off > 0; off >>= 1)
        s += __shfl_down_sync(0xffffffffu, s, off);
    if ((threadIdx.x & 31) == 0) wsum[threadIdx.x >> 5] = s;
    __syncthreads();

    const int b = __ldg(&batch[n]);
    for (int k = threadIdx.x; k < D_; k += 128)
        atomicAdd(&pooled[b * DP1_ + k], hrow[k]);
    if (threadIdx.x == 0) {
        float ks = wsum[0] + wsum[1] + wsum[2] + wsum[3];
        atomicAdd(&pooled[b * DP1_ + D_], ks);
        atomicAdd(&cnt[b], 1.0f);
    }
}

// ---------------- final MLP per graph ----------------
__global__ __launch_bounds__(256) void final_mlp_kernel(
    const float* __restrict__ pooled, const float* __restrict__ cnt,
    const float* __restrict__ Wo1, const float* __restrict__ bo1,
    const float* __restrict__ Wo2, const float* __restrict__ bo2,
    float* __restrict__ out)
{
    const int g = blockIdx.x;
    __shared__ float p[DP1_];
    __shared__ float hid[HID_];
    const float c = fmaxf(cnt[g], 1.0f);
    for (int k = threadIdx.x; k < DP1_; k += 256)
        p[k] = pooled[g * DP1_ + k] / c;
    __syncthreads();

    const int j = threadIdx.x;
    float s = __ldg(&bo1[j]);
    for (int k = 0; k < DP1_; k++)
        s = fmaf(p[k], __ldg(&Wo1[k * HID_ + j]), s);
    hid[j] = silu_f(s);
    __syncthreads();

    if (j < OUT_) {
        float o = __ldg(&bo2[j]);
        for (int k = 0; k < HID_; k++)
            o = fmaf(hid[k], __ldg(&Wo2[k * OUT_ + j]), o);
        out[g * OUT_ + j] = o;
    }
}

// ---------------- host driver ----------------
static inline dim3 gemm_grid(int M, int N) {
    return dim3((N + BN - 1) / BN, (M + BM - 1) / BM);
}

extern "C" void kernel_launch(void* const* d_in, const int* in_sizes, int n_in,
                              void* d_out, int out_size)
{
    const float* x     = (const float*)d_in[0];
    const int*   ei    = (const int*)  d_in[1];
    const int*   batch = (const int*)  d_in[2];
    const int*   sci   = (const int*)  d_in[3];
    const int*   scj   = (const int*)  d_in[4];
    const int*   sck   = (const int*)  d_in[5];
    const float* scc   = (const float*)d_in[6];
    const int*   kbr   = (const int*)  d_in[7];
    const int*   kbc   = (const int*)  d_in[8];
    const float* kbv   = (const float*)d_in[9];
    const float* Wi1   = (const float*)d_in[10];
    const float* bi1   = (const float*)d_in[11];
    const float* Wi2   = (const float*)d_in[12];
    const float* bi2   = (const float*)d_in[13];
    const float* msgW1 = (const float*)d_in[14];
    const float* msgb1 = (const float*)d_in[15];
    const float* msgW2 = (const float*)d_in[16];
    const float* msgb2 = (const float*)d_in[17];
    const float* updW1 = (const float*)d_in[18];
    const float* updb1 = (const float*)d_in[19];
    const float* updW2 = (const float*)d_in[20];
    const float* updb2 = (const float*)d_in[21];
    const float* Wo1   = (const float*)d_in[22];
    const float* bo1   = (const float*)d_in[23];
    const float* Wo2   = (const float*)d_in[24];
    const float* bo2   = (const float*)d_in[25];

    float *t1, *h, *br, *eH, *agg, *pooled, *cnt;
    cudaGetSymbolAddress((void**)&t1,     g_t1);
    cudaGetSymbolAddress((void**)&h,      g_h);
    cudaGetSymbolAddress((void**)&br,     g_br);
    cudaGetSymbolAddress((void**)&eH,     g_eH);
    cudaGetSymbolAddress((void**)&agg,    g_agg);
    cudaGetSymbolAddress((void**)&pooled, g_pooled);
    cudaGetSymbolAddress((void**)&cnt,    g_cnt);

    const int* src = ei;
    const int* dst = ei + E_;

    // ---- input MLP: h = silu(x@Wi1+b)@Wi2+b ----
    gemm_3xbf16<<<gemm_grid(N_, HID_), 256>>>(x,  nullptr, x,  IN_,  Wi1, bi1, nullptr, nullptr, t1, N_, HID_, IN_,  1);
    gemm_3xbf16<<<gemm_grid(N_, D_),   256>>>(t1, nullptr, t1, HID_, Wi2, bi2, nullptr, nullptr, h,  N_, D_,   HID_, 0);

    // ---- message passing layers ----
    for (int l = 0; l < NL_; l++) {
        const float* mW1 = msgW1 + (size_t)l * D2_ * HID_;
        const float* mb1 = msgb1 + (size_t)l * HID_;
        const float* mW2 = msgW2 + (size_t)l * HID_ * D_;
        const float* mb2 = msgb2 + (size_t)l * D_;
        const float* uW1 = updW1 + (size_t)l * D2_ * HID_;
        const float* ub1 = updb1 + (size_t)l * HID_;
        const float* uW2 = updW2 + (size_t)l * HID_ * D_;
        const float* ub2 = updb2 + (size_t)l * D_;

        edge_bracket_kernel<<<(E_ + EPB - 1) / EPB, 256>>>(h, ei, sci, scj, sck, scc, br);

        // message MLP layer 1: A = [h[src] | br]
        gemm_3xbf16<<<gemm_grid(E_, HID_), 256>>>(h,  src, br, D_, mW1, mb1, nullptr, nullptr, eH, E_, HID_, D2_, 1);

        // zero agg, then message MLP layer 2 with fused scatter-add into agg
        {
            size_t n = (size_t)N_ * D_;
            zero_kernel<<<(unsigned)((n + 255) / 256), 256>>>(agg, n);
        }
        gemm_3xbf16<<<gemm_grid(E_, D_), 256>>>(eH, nullptr, eH, HID_, mW2, mb2, nullptr, dst, agg, E_, D_, HID_, 0);

        // update MLP: A = [h | agg]
        gemm_3xbf16<<<gemm_grid(N_, HID_), 256>>>(h,  nullptr, agg, D_,  uW1, ub1, nullptr, nullptr, t1, N_, HID_, D2_, 1);
        gemm_3xbf16<<<gemm_grid(N_, D_),   256>>>(t1, nullptr, t1,  HID_, uW2, ub2, h,      nullptr, h,  N_, D_,   HID_, 0);
    }

    // ---- killing form + pooling ----
    {
        size_t n = NG_ * DP1_;
        zero_kernel<<<(unsigned)((n + 255) / 256), 256>>>(pooled, n);
        zero_kernel<<<1, NG_>>>(cnt, NG_);
    }
    killing_pool_kernel<<<N_, 128>>>(h, batch, kbr, kbc, kbv, pooled, cnt);

    // ---- final MLP ----
    final_mlp_kernel<<<NG_, 256>>>(pooled, cnt, Wo1, bo1, Wo2, bo2, (float*)d_out);
}